// round 3
// baseline (speedup 1.0000x reference)
#include <cuda_runtime.h>
#include <math.h>

#define CB  32
#define CNS 4096
#define CD  256
#define CH  4
#define CDH 64
#define CL  6
#define CNQ 512
#define CNK 1024
#define SCALE_F 0.125f   // 1/sqrt(64)

// ------------------------- scratch (device globals; no allocs) -------------
__device__ float g_upd[CB*CNS*CD];   // working copy of update_tensor
__device__ float g_q  [CB*CNQ*CD];
__device__ float g_k  [CB*CNK*CD];
__device__ float g_Qp [CB*CNQ*CD];
__device__ float g_Kp [CB*CNK*CD];
__device__ float g_Vp [CB*CNK*CD];
__device__ float g_ctx[CB*CNQ*CD];
__device__ float g_h  [CB*CNQ*CD];
__device__ float g_t1 [CB*CNQ*CD];
__device__ float g_t2 [CB*CNQ*CD];

// ------------------------- helpers ----------------------------------------
__device__ __forceinline__ float gelu_tanh(float x){
    // jax.nn.gelu default (approximate=True)
    float x3 = x*x*x;
    float t  = tanhf(0.7978845608028654f * (x + 0.044715f * x3));
    return 0.5f * x * (1.0f + t);
}

// ------------------------- init copy ---------------------------------------
__global__ void k_copy_upd(const float4* __restrict__ src){
    size_t i = (size_t)blockIdx.x * blockDim.x + threadIdx.x;
    ((float4*)g_upd)[i] = src[i];
}

// ------------------------- gather + LayerNorm ------------------------------
// out[row] = LN(emb[idx[p]] + upd[b, idx[p], :]) ; row = b*N + p ; 256 thr/row
__global__ void k_gather_ln(const float* __restrict__ upd,
                            const float* __restrict__ emb,
                            const int*   __restrict__ idx,
                            const float* __restrict__ sc,
                            const float* __restrict__ bi,
                            float* __restrict__ out, int N){
    __shared__ float sbuf[16];
    int row = blockIdx.x;
    int b = row / N, p = row - b*N;
    int node = idx[p];
    int t = threadIdx.x;
    float x = emb[(size_t)node*CD + t] + upd[((size_t)b*CNS + node)*CD + t];
    float s1 = x, s2 = x*x;
    #pragma unroll
    for(int o=16;o>0;o>>=1){
        s1 += __shfl_xor_sync(0xffffffffu, s1, o);
        s2 += __shfl_xor_sync(0xffffffffu, s2, o);
    }
    if((t&31)==0){ sbuf[t>>5]=s1; sbuf[8+(t>>5)]=s2; }
    __syncthreads();
    s1=0.f; s2=0.f;
    #pragma unroll
    for(int i=0;i<8;i++){ s1+=sbuf[i]; s2+=sbuf[8+i]; }
    float mean = s1 * (1.0f/CD);
    float var  = s2 * (1.0f/CD) - mean*mean;
    float rstd = rsqrtf(var + 1e-5f);
    out[(size_t)row*CD + t] = (x-mean)*rstd*sc[t] + bi[t];
}

// ------------------------- plain row LayerNorm -----------------------------
__global__ void k_ln(const float* __restrict__ in,
                     const float* __restrict__ sc,
                     const float* __restrict__ bi,
                     float* __restrict__ out){
    __shared__ float sbuf[16];
    int row = blockIdx.x;
    int t = threadIdx.x;
    float x = in[(size_t)row*CD + t];
    float s1 = x, s2 = x*x;
    #pragma unroll
    for(int o=16;o>0;o>>=1){
        s1 += __shfl_xor_sync(0xffffffffu, s1, o);
        s2 += __shfl_xor_sync(0xffffffffu, s2, o);
    }
    if((t&31)==0){ sbuf[t>>5]=s1; sbuf[8+(t>>5)]=s2; }
    __syncthreads();
    s1=0.f; s2=0.f;
    #pragma unroll
    for(int i=0;i<8;i++){ s1+=sbuf[i]; s2+=sbuf[8+i]; }
    float mean = s1 * (1.0f/CD);
    float var  = s2 * (1.0f/CD) - mean*mean;
    float rstd = rsqrtf(var + 1e-5f);
    out[(size_t)row*CD + t] = (x-mean)*rstd*sc[t] + bi[t];
}

// ------------------------- SGEMM: C[M,256] = A[M,256] @ W[256,256] ---------
// BM=128 BN=64 BK=16, 256 threads, 8x4 micro-tile. act: 0=none, 1=gelu.
__global__ void __launch_bounds__(256)
k_gemm(const float* __restrict__ A, const float* __restrict__ W,
       const float* __restrict__ bias, float* __restrict__ C, int act){
    __shared__ float As[16][132];   // transposed A tile, padded (132*4B % 16B == 0)
    __shared__ float Bs[16][64];
    int tid = threadIdx.x;
    int tx = tid & 15, ty = tid >> 4;
    int bm0 = blockIdx.x * 128;
    int bn0 = blockIdx.y * 64;
    const float* Ab = A + (size_t)bm0 * CD;

    float acc[8][4];
    #pragma unroll
    for(int i=0;i<8;i++)
        #pragma unroll
        for(int j=0;j<4;j++) acc[i][j]=0.f;

    for(int k0=0;k0<CD;k0+=16){
        // load A tile 128x16 (transposed into As[k][m])
        #pragma unroll
        for(int i=0;i<8;i++){
            int lin = tid + i*256;
            int m = lin >> 4, kk = lin & 15;
            As[kk][m] = Ab[(size_t)m*CD + k0 + kk];
        }
        // load B tile 16x64 (one float4 per thread)
        {
            int kk = tid >> 4, n4 = tid & 15;
            *(float4*)&Bs[kk][n4*4] =
                *(const float4*)&W[(size_t)(k0+kk)*CD + bn0 + n4*4];
        }
        __syncthreads();
        #pragma unroll
        for(int kk=0;kk<16;kk++){
            float4 a0 = *(float4*)&As[kk][ty*8];
            float4 a1 = *(float4*)&As[kk][ty*8+4];
            float4 b0 = *(float4*)&Bs[kk][tx*4];
            float a[8] = {a0.x,a0.y,a0.z,a0.w,a1.x,a1.y,a1.z,a1.w};
            float bb[4] = {b0.x,b0.y,b0.z,b0.w};
            #pragma unroll
            for(int i=0;i<8;i++)
                #pragma unroll
                for(int j=0;j<4;j++) acc[i][j] += a[i]*bb[j];
        }
        __syncthreads();
    }
    // epilogue
    float bv[4] = {0.f,0.f,0.f,0.f};
    if(bias){
        float4 b4 = *(const float4*)&bias[bn0 + tx*4];
        bv[0]=b4.x; bv[1]=b4.y; bv[2]=b4.z; bv[3]=b4.w;
    }
    #pragma unroll
    for(int i=0;i<8;i++){
        int m = bm0 + ty*8 + i;
        float4 r;
        float* rp = &r.x;
        #pragma unroll
        for(int j=0;j<4;j++){
            float v = acc[i][j] + bv[j];
            if(act==1) v = gelu_tanh(v);
            rp[j] = v;
        }
        *(float4*)&C[(size_t)m*CD + bn0 + tx*4] = r;
    }
}

// ------------------------- attention (flash-style, fp32) -------------------
// grid (NQ/8, H, B), 256 threads = 8 warps; warp w handles q = bx*8+w.
// Lane-per-key scoring on 32-key smem tiles; online softmax; shfl-broadcast PV.
__global__ void __launch_bounds__(256)
k_attn(const float* __restrict__ Q, const float* __restrict__ K,
       const float* __restrict__ V, const float* __restrict__ mask,
       float* __restrict__ ctx){
    __shared__ float Kt[32][68];   // 68*4B=272B rows: 16B aligned, conflict-free f4
    __shared__ float Vt[32][68];
    __shared__ float qs[8][68];
    int tid = threadIdx.x, w = tid>>5, lane = tid&31;
    int b = blockIdx.z, h = blockIdx.y;
    int q = blockIdx.x*8 + w;

    const float* qrow = Q + ((size_t)(b*CNQ + q))*CD + h*CDH;
    float2 qv = *(const float2*)&qrow[lane*2];
    qs[w][lane*2]   = qv.x;
    qs[w][lane*2+1] = qv.y;
    __syncwarp();

    float   mrun  = -INFINITY;
    float   denom = 0.f;
    float2  acc   = make_float2(0.f, 0.f);

    const float* Kb   = K + ((size_t)b*CNK)*CD + h*CDH;
    const float* Vb   = V + ((size_t)b*CNK)*CD + h*CDH;
    const float* mrow = mask + (size_t)q*CNK;

    for(int k0=0;k0<CNK;k0+=32){
        // cooperative load of 32x64 K and V tiles
        #pragma unroll
        for(int i=0;i<2;i++){
            int f = tid + i*256;
            int r = f >> 4, c4 = f & 15;
            *(float4*)&Kt[r][c4*4] = *(const float4*)&Kb[(size_t)(k0+r)*CD + c4*4];
            *(float4*)&Vt[r][c4*4] = *(const float4*)&Vb[(size_t)(k0+r)*CD + c4*4];
        }
        __syncthreads();

        // score for key (k0+lane): 64-dim dot, 4 partial chains
        float4 ps4 = make_float4(0.f,0.f,0.f,0.f);
        #pragma unroll
        for(int d4=0; d4<16; d4++){
            float4 kk4 = *(float4*)&Kt[lane][d4*4];
            float4 qq4 = *(float4*)&qs[w][d4*4];
            ps4.x += qq4.x*kk4.x; ps4.y += qq4.y*kk4.y;
            ps4.z += qq4.z*kk4.z; ps4.w += qq4.w*kk4.w;
        }
        float s = (ps4.x+ps4.y)+(ps4.z+ps4.w);
        float mval = mrow[k0 + lane];
        s = (mval > 0.5f) ? s*SCALE_F : -1e9f;

        // online softmax
        float tm = s;
        #pragma unroll
        for(int o=16;o>0;o>>=1) tm = fmaxf(tm, __shfl_xor_sync(0xffffffffu, tm, o));
        float mn    = fmaxf(mrun, tm);
        float alpha = __expf(mrun - mn);
        float p     = __expf(s - mn);
        float psum  = p;
        #pragma unroll
        for(int o=16;o>0;o>>=1) psum += __shfl_xor_sync(0xffffffffu, psum, o);
        denom = denom*alpha + psum;
        mrun  = mn;
        acc.x *= alpha; acc.y *= alpha;

        // PV accumulation: broadcast p per key, lanes own 2 dims
        #pragma unroll
        for(int ki=0;ki<32;ki++){
            float pk = __shfl_sync(0xffffffffu, p, ki);
            float2 v = *(float2*)&Vt[ki][lane*2];
            acc.x += pk*v.x;
            acc.y += pk*v.y;
        }
        __syncthreads();
    }
    float inv = 1.0f/denom;
    float2 o  = make_float2(acc.x*inv, acc.y*inv);
    *(float2*)&ctx[((size_t)(b*CNQ+q))*CD + h*CDH + lane*2] = o;
}

// ------------------------- h+ffn, double LN, scatter-add -------------------
__global__ void k_final(const float* __restrict__ h, const float* __restrict__ t2,
                        const float* __restrict__ os, const float* __restrict__ ob,
                        const float* __restrict__ es, const float* __restrict__ eb,
                        const int*   __restrict__ qidx,
                        float* __restrict__ upd, float* __restrict__ outp){
    __shared__ float sbuf[16];
    int row = blockIdx.x;
    int b = row >> 9, p = row & (CNQ-1);
    int t = threadIdx.x;
    float x = h[(size_t)row*CD + t] + t2[(size_t)row*CD + t];

    // LN outer
    float s1 = x, s2 = x*x;
    #pragma unroll
    for(int o=16;o>0;o>>=1){
        s1 += __shfl_xor_sync(0xffffffffu, s1, o);
        s2 += __shfl_xor_sync(0xffffffffu, s2, o);
    }
    if((t&31)==0){ sbuf[t>>5]=s1; sbuf[8+(t>>5)]=s2; }
    __syncthreads();
    s1=0.f; s2=0.f;
    #pragma unroll
    for(int i=0;i<8;i++){ s1+=sbuf[i]; s2+=sbuf[8+i]; }
    float mean = s1*(1.0f/CD);
    float var  = s2*(1.0f/CD) - mean*mean;
    float rstd = rsqrtf(var + 1e-5f);
    float y = (x-mean)*rstd*os[t] + ob[t];
    __syncthreads();

    // LN eff
    s1 = y; s2 = y*y;
    #pragma unroll
    for(int o=16;o>0;o>>=1){
        s1 += __shfl_xor_sync(0xffffffffu, s1, o);
        s2 += __shfl_xor_sync(0xffffffffu, s2, o);
    }
    if((t&31)==0){ sbuf[t>>5]=s1; sbuf[8+(t>>5)]=s2; }
    __syncthreads();
    s1=0.f; s2=0.f;
    #pragma unroll
    for(int i=0;i<8;i++){ s1+=sbuf[i]; s2+=sbuf[8+i]; }
    float mean2 = s1*(1.0f/CD);
    float var2  = s2*(1.0f/CD) - mean2*mean2;
    float rstd2 = rsqrtf(var2 + 1e-5f);
    float res = (y-mean2)*rstd2*es[t] + eb[t];

    int node = qidx[p];
    size_t off = ((size_t)(b*CNS + node))*CD + t;
    atomicAdd(&upd[off],  res);
    atomicAdd(&outp[off], res);
}

// ------------------------- launch ------------------------------------------
extern "C" void kernel_launch(void* const* d_in, const int* in_sizes, int n_in,
                              void* d_out, int out_size){
    const float* in_upd  = (const float*)d_in[0];
    const float* emb     = (const float*)d_in[1];
    const float* maskL   = (const float*)d_in[2];
    const float* Wq      = (const float*)d_in[3];
    const float* Wk      = (const float*)d_in[4];
    const float* Wv      = (const float*)d_in[5];
    const float* Wo      = (const float*)d_in[6];
    const float* W1      = (const float*)d_in[7];
    const float* b1      = (const float*)d_in[8];
    const float* W2      = (const float*)d_in[9];
    const float* b2      = (const float*)d_in[10];
    const float* sys_s   = (const float*)d_in[11];
    const float* sys_b   = (const float*)d_in[12];
    const float* eff_s   = (const float*)d_in[13];
    const float* eff_b   = (const float*)d_in[14];
    const float* in_s    = (const float*)d_in[15];
    const float* in_b    = (const float*)d_in[16];
    const float* out_s   = (const float*)d_in[17];
    const float* out_b   = (const float*)d_in[18];
    const int*   qidxL   = (const int*)d_in[19];
    const int*   kidxL   = (const int*)d_in[20];
    float* outp = (float*)d_out;

    float *upd,*qb,*kb,*Qb,*Kb,*Vb,*ctx,*hb,*t1,*t2;
    cudaGetSymbolAddress((void**)&upd, g_upd);
    cudaGetSymbolAddress((void**)&qb,  g_q);
    cudaGetSymbolAddress((void**)&kb,  g_k);
    cudaGetSymbolAddress((void**)&Qb,  g_Qp);
    cudaGetSymbolAddress((void**)&Kb,  g_Kp);
    cudaGetSymbolAddress((void**)&Vb,  g_Vp);
    cudaGetSymbolAddress((void**)&ctx, g_ctx);
    cudaGetSymbolAddress((void**)&hb,  g_h);
    cudaGetSymbolAddress((void**)&t1,  g_t1);
    cudaGetSymbolAddress((void**)&t2,  g_t2);

    cudaMemsetAsync(d_out, 0, (size_t)out_size * sizeof(float));
    k_copy_upd<<<(CB*CNS*CD/4)/256, 256>>>((const float4*)in_upd);

    for(int l=0;l<CL;l++){
        const int*   qi  = qidxL + l*CNQ;
        const int*   ki  = kidxL + l*CNK;
        const float* msk = maskL + (size_t)l*CNQ*CNK;

        k_gather_ln<<<CB*CNQ, 256>>>(upd, emb, qi, sys_s, sys_b, qb, CNQ);
        k_gather_ln<<<CB*CNK, 256>>>(upd, emb, ki, sys_s, sys_b, kb, CNK);

        k_gemm<<<dim3(CB*CNQ/128, 4), 256>>>(qb, Wq, nullptr, Qb, 0);
        k_gemm<<<dim3(CB*CNK/128, 4), 256>>>(kb, Wk, nullptr, Kb, 0);
        k_gemm<<<dim3(CB*CNK/128, 4), 256>>>(kb, Wv, nullptr, Vb, 0);

        k_attn<<<dim3(CNQ/8, CH, CB), 256>>>(Qb, Kb, Vb, msk, ctx);

        k_gemm<<<dim3(CB*CNQ/128, 4), 256>>>(ctx, Wo, nullptr, t1, 0);
        k_ln  <<<CB*CNQ, 256>>>(t1, in_s, in_b, hb);

        k_gemm<<<dim3(CB*CNQ/128, 4), 256>>>(hb, W1, b1, t1, 1);   // gelu
        k_gemm<<<dim3(CB*CNQ/128, 4), 256>>>(t1, W2, b2, t2, 0);

        k_final<<<CB*CNQ, 256>>>(hb, t2, out_s, out_b, eff_s, eff_b,
                                 qi, upd, outp);
    }
}

// round 4
// speedup vs baseline: 4.1258x; 4.1258x over previous
#include <cuda_runtime.h>
#include <mma.h>
#include <math.h>

using namespace nvcuda;

#define CB  32
#define CNS 4096
#define CD  256
#define CH  4
#define CDH 64
#define CL  6
#define CNQ 512
#define CNK 1024
#define SCALE_F 0.125f   // 1/sqrt(64)

// ------------------------- scratch (device globals; no allocs) -------------
__device__ float g_upd[CB*CNS*CD];   // working copy of update_tensor
__device__ float g_q  [CB*CNQ*CD];
__device__ float g_k  [CB*CNK*CD];
__device__ float g_Qp [CB*CNQ*CD];
__device__ float g_Kp [CB*CNK*CD];
__device__ float g_Vp [CB*CNK*CD];
__device__ float g_ctx[CB*CNQ*CD];
__device__ float g_h  [CB*CNQ*CD];
__device__ float g_t1 [CB*CNQ*CD];
__device__ float g_t2 [CB*CNQ*CD];
__device__ float g_S  [(size_t)CB*CH*CNQ*CNK];   // scores / probs (268MB)

// ------------------------- helpers ----------------------------------------
__device__ __forceinline__ float gelu_tanh(float x){
    float x3 = x*x*x;
    float t  = tanhf(0.7978845608028654f * (x + 0.044715f * x3));
    return 0.5f * x * (1.0f + t);
}
__device__ __forceinline__ float to_tf32(float x){
    return wmma::__float_to_tf32(x);
}

// ------------------------- init copy ---------------------------------------
__global__ void k_copy_upd(const float4* __restrict__ src){
    size_t i = (size_t)blockIdx.x * blockDim.x + threadIdx.x;
    ((float4*)g_upd)[i] = src[i];
}

// ------------------------- gather + LayerNorm ------------------------------
__global__ void k_gather_ln(const float* __restrict__ upd,
                            const float* __restrict__ emb,
                            const int*   __restrict__ idx,
                            const float* __restrict__ sc,
                            const float* __restrict__ bi,
                            float* __restrict__ out, int N){
    __shared__ float sbuf[16];
    int row = blockIdx.x;
    int b = row / N, p = row - b*N;
    int node = idx[p];
    int t = threadIdx.x;
    float x = emb[(size_t)node*CD + t] + upd[((size_t)b*CNS + node)*CD + t];
    float s1 = x, s2 = x*x;
    #pragma unroll
    for(int o=16;o>0;o>>=1){
        s1 += __shfl_xor_sync(0xffffffffu, s1, o);
        s2 += __shfl_xor_sync(0xffffffffu, s2, o);
    }
    if((t&31)==0){ sbuf[t>>5]=s1; sbuf[8+(t>>5)]=s2; }
    __syncthreads();
    s1=0.f; s2=0.f;
    #pragma unroll
    for(int i=0;i<8;i++){ s1+=sbuf[i]; s2+=sbuf[8+i]; }
    float mean = s1 * (1.0f/CD);
    float var  = s2 * (1.0f/CD) - mean*mean;
    float rstd = rsqrtf(var + 1e-5f);
    out[(size_t)row*CD + t] = (x-mean)*rstd*sc[t] + bi[t];
}

// ------------------------- plain row LayerNorm -----------------------------
__global__ void k_ln(const float* __restrict__ in,
                     const float* __restrict__ sc,
                     const float* __restrict__ bi,
                     float* __restrict__ out){
    __shared__ float sbuf[16];
    int row = blockIdx.x;
    int t = threadIdx.x;
    float x = in[(size_t)row*CD + t];
    float s1 = x, s2 = x*x;
    #pragma unroll
    for(int o=16;o>0;o>>=1){
        s1 += __shfl_xor_sync(0xffffffffu, s1, o);
        s2 += __shfl_xor_sync(0xffffffffu, s2, o);
    }
    if((t&31)==0){ sbuf[t>>5]=s1; sbuf[8+(t>>5)]=s2; }
    __syncthreads();
    s1=0.f; s2=0.f;
    #pragma unroll
    for(int i=0;i<8;i++){ s1+=sbuf[i]; s2+=sbuf[8+i]; }
    float mean = s1 * (1.0f/CD);
    float var  = s2 * (1.0f/CD) - mean*mean;
    float rstd = rsqrtf(var + 1e-5f);
    out[(size_t)row*CD + t] = (x-mean)*rstd*sc[t] + bi[t];
}

// ===================== TF32 WMMA dense GEMM ================================
// C[M,256] = A[M,256] @ W[256,256] (+bias)(+gelu). Block tile 128x64,
// 8 warps (4x2), warp tile 32x32 = 2x2 m16n16k8 frags. act: 0 none, 1 gelu.
__global__ void __launch_bounds__(256)
k_gemm_tc(const float* __restrict__ A, const float* __restrict__ W,
          const float* __restrict__ bias, float* __restrict__ C, int act){
    __shared__ __align__(16) float As[128][40];
    __shared__ __align__(16) float Bs[32][72];
    __shared__ __align__(16) float BiasS[16][72];
    int tid = threadIdx.x;
    int w = tid >> 5;
    int wy = w >> 1, wx = w & 1;           // 4 x 2 warps
    int bm0 = blockIdx.x * 128;
    int bn0 = blockIdx.y * 64;

    wmma::fragment<wmma::accumulator,16,16,8,float> acc[2][2];
    #pragma unroll
    for(int i=0;i<2;i++)
        #pragma unroll
        for(int j=0;j<2;j++) wmma::fill_fragment(acc[i][j], 0.0f);

    for(int k0=0;k0<CD;k0+=32){
        // A tile 128x32 (tf32-rounded)
        #pragma unroll
        for(int i=0;i<4;i++){
            int id = tid + i*256;
            int r = id >> 3, c4 = id & 7;
            float4 v = *(const float4*)&A[(size_t)(bm0+r)*CD + k0 + c4*4];
            float* d = &As[r][c4*4];
            d[0]=to_tf32(v.x); d[1]=to_tf32(v.y); d[2]=to_tf32(v.z); d[3]=to_tf32(v.w);
        }
        // B tile 32x64
        #pragma unroll
        for(int i=0;i<2;i++){
            int id = tid + i*256;
            int r = id >> 4, c4 = id & 15;
            float4 v = *(const float4*)&W[(size_t)(k0+r)*CD + bn0 + c4*4];
            float* d = &Bs[r][c4*4];
            d[0]=to_tf32(v.x); d[1]=to_tf32(v.y); d[2]=to_tf32(v.z); d[3]=to_tf32(v.w);
        }
        __syncthreads();
        #pragma unroll
        for(int ks=0;ks<4;ks++){
            wmma::fragment<wmma::matrix_a,16,16,8,wmma::precision::tf32,wmma::row_major> af[2];
            wmma::fragment<wmma::matrix_b,16,16,8,wmma::precision::tf32,wmma::row_major> bf[2];
            wmma::load_matrix_sync(af[0], &As[wy*32][ks*8],    40);
            wmma::load_matrix_sync(af[1], &As[wy*32+16][ks*8], 40);
            wmma::load_matrix_sync(bf[0], &Bs[ks*8][wx*32],    72);
            wmma::load_matrix_sync(bf[1], &Bs[ks*8][wx*32+16], 72);
            #pragma unroll
            for(int i=0;i<2;i++)
                #pragma unroll
                for(int j=0;j<2;j++)
                    wmma::mma_sync(acc[i][j], af[i], bf[j], acc[i][j]);
        }
        __syncthreads();
    }

    // bias (replicated rows) -> accumulator-layout fragment
    if(bias){
        #pragma unroll
        for(int i=0;i<4;i++){
            int id = tid + i*256;      // 16x64 = 1024 elems
            int r = id >> 6, c = id & 63;
            BiasS[r][c] = bias[bn0 + c];
        }
        __syncthreads();
        #pragma unroll
        for(int j=0;j<2;j++){
            wmma::fragment<wmma::accumulator,16,16,8,float> bfr;
            wmma::load_matrix_sync(bfr, &BiasS[0][wx*32 + j*16], 72, wmma::mem_row_major);
            #pragma unroll
            for(int i=0;i<2;i++)
                #pragma unroll
                for(int e=0;e<bfr.num_elements;e++)
                    acc[i][j].x[e] += bfr.x[e];
        }
    }
    if(act==1){
        #pragma unroll
        for(int i=0;i<2;i++)
            #pragma unroll
            for(int j=0;j<2;j++)
                #pragma unroll
                for(int e=0;e<acc[i][j].num_elements;e++)
                    acc[i][j].x[e] = gelu_tanh(acc[i][j].x[e]);
    }
    #pragma unroll
    for(int i=0;i<2;i++)
        #pragma unroll
        for(int j=0;j<2;j++)
            wmma::store_matrix_sync(
                &C[(size_t)(bm0 + wy*32 + i*16)*CD + bn0 + wx*32 + j*16],
                acc[i][j], CD, wmma::mem_row_major);
}

// ===================== attention GEMM1: S = (Q K^T) * SCALE ================
// grid (NQ/64, NK/128, B*H), block 256 = 8 warps (2x4), warp 32q x 32k.
__global__ void __launch_bounds__(256)
k_qk(const float* __restrict__ Q, const float* __restrict__ K,
     float* __restrict__ S){
    __shared__ __align__(16) float Qs[64][40];
    __shared__ __align__(16) float Ks[128][40];
    int tid = threadIdx.x;
    int w = tid >> 5;
    int wy = w >> 2, wx = w & 3;          // 2 x 4 warps
    int q0 = blockIdx.x * 64;
    int k0 = blockIdx.y * 128;
    int bh = blockIdx.z;
    int b = bh >> 2, h = bh & 3;

    const float* Qb = Q + ((size_t)b*CNQ)*CD + h*CDH;
    const float* Kb = K + ((size_t)b*CNK)*CD + h*CDH;

    wmma::fragment<wmma::accumulator,16,16,8,float> acc[2][2];
    #pragma unroll
    for(int i=0;i<2;i++)
        #pragma unroll
        for(int j=0;j<2;j++) wmma::fill_fragment(acc[i][j], 0.0f);

    #pragma unroll
    for(int d0=0; d0<CDH; d0+=32){
        // Q tile 64x32
        #pragma unroll
        for(int i=0;i<2;i++){
            int id = tid + i*256;
            int r = id >> 3, c4 = id & 7;
            float4 v = *(const float4*)&Qb[(size_t)(q0+r)*CD + d0 + c4*4];
            float* d = &Qs[r][c4*4];
            d[0]=to_tf32(v.x); d[1]=to_tf32(v.y); d[2]=to_tf32(v.z); d[3]=to_tf32(v.w);
        }
        // K tile 128x32
        #pragma unroll
        for(int i=0;i<4;i++){
            int id = tid + i*256;
            int r = id >> 3, c4 = id & 7;
            float4 v = *(const float4*)&Kb[(size_t)(k0+r)*CD + d0 + c4*4];
            float* d = &Ks[r][c4*4];
            d[0]=to_tf32(v.x); d[1]=to_tf32(v.y); d[2]=to_tf32(v.z); d[3]=to_tf32(v.w);
        }
        __syncthreads();
        #pragma unroll
        for(int ks=0;ks<4;ks++){
            wmma::fragment<wmma::matrix_a,16,16,8,wmma::precision::tf32,wmma::row_major> af[2];
            wmma::fragment<wmma::matrix_b,16,16,8,wmma::precision::tf32,wmma::col_major> bf[2];
            wmma::load_matrix_sync(af[0], &Qs[wy*32][ks*8],    40);
            wmma::load_matrix_sync(af[1], &Qs[wy*32+16][ks*8], 40);
            wmma::load_matrix_sync(bf[0], &Ks[wx*32][ks*8],    40);   // col_major: (d, key)
            wmma::load_matrix_sync(bf[1], &Ks[wx*32+16][ks*8], 40);
            #pragma unroll
            for(int i=0;i<2;i++)
                #pragma unroll
                for(int j=0;j<2;j++)
                    wmma::mma_sync(acc[i][j], af[i], bf[j], acc[i][j]);
        }
        __syncthreads();
    }
    float* Srow = S + ((size_t)bh*CNQ)*CNK;
    #pragma unroll
    for(int i=0;i<2;i++)
        #pragma unroll
        for(int j=0;j<2;j++){
            #pragma unroll
            for(int e=0;e<acc[i][j].num_elements;e++)
                acc[i][j].x[e] *= SCALE_F;
            wmma::store_matrix_sync(
                &Srow[(size_t)(q0 + wy*32 + i*16)*CNK + k0 + wx*32 + j*16],
                acc[i][j], CNK, wmma::mem_row_major);
        }
}

// ===================== masked softmax over k (in place) ====================
// grid (NQ, B*H), block 256; each thread owns 4 contiguous keys.
__global__ void __launch_bounds__(256)
k_softmax(float* __restrict__ S, const float* __restrict__ mask){
    __shared__ float red[8];
    int q = blockIdx.x, bh = blockIdx.y;
    int t = threadIdx.x, w = t>>5, lane = t&31;
    float* row = S + ((size_t)bh*CNQ + q)*CNK;
    const float* mrow = mask + (size_t)q*CNK;

    float4 s4 = *(float4*)&row[t*4];
    float4 m4 = *(const float4*)&mrow[t*4];
    float v0 = (m4.x>0.5f)? s4.x : -1e9f;
    float v1 = (m4.y>0.5f)? s4.y : -1e9f;
    float v2 = (m4.z>0.5f)? s4.z : -1e9f;
    float v3 = (m4.w>0.5f)? s4.w : -1e9f;

    float mx = fmaxf(fmaxf(v0,v1), fmaxf(v2,v3));
    #pragma unroll
    for(int o=16;o>0;o>>=1) mx = fmaxf(mx, __shfl_xor_sync(0xffffffffu, mx, o));
    if(lane==0) red[w] = mx;
    __syncthreads();
    mx = red[0];
    #pragma unroll
    for(int i=1;i<8;i++) mx = fmaxf(mx, red[i]);

    float e0 = __expf(v0-mx), e1 = __expf(v1-mx);
    float e2 = __expf(v2-mx), e3 = __expf(v3-mx);
    float sm = (e0+e1)+(e2+e3);
    #pragma unroll
    for(int o=16;o>0;o>>=1) sm += __shfl_xor_sync(0xffffffffu, sm, o);
    __syncthreads();
    if(lane==0) red[w] = sm;
    __syncthreads();
    sm = 0.f;
    #pragma unroll
    for(int i=0;i<8;i++) sm += red[i];
    float inv = 1.0f/sm;
    float4 p4 = make_float4(e0*inv, e1*inv, e2*inv, e3*inv);
    *(float4*)&row[t*4] = p4;
}

// ===================== attention GEMM2: ctx = P @ V ========================
// grid (NQ/128, B*H), block 256 = 8 warps (4x2), warp 32q x 32d.
__global__ void __launch_bounds__(256)
k_pv(const float* __restrict__ P, const float* __restrict__ V,
     float* __restrict__ ctx){
    __shared__ __align__(16) float Ps[128][40];
    __shared__ __align__(16) float Vs[32][72];
    int tid = threadIdx.x;
    int w = tid >> 5;
    int wy = w >> 1, wx = w & 1;          // 4 x 2 warps (d tiles 0,32)
    int q0 = blockIdx.x * 128;
    int bh = blockIdx.y;
    int b = bh >> 2, h = bh & 3;

    const float* Pb = P + ((size_t)bh*CNQ)*CNK;
    const float* Vb = V + ((size_t)b*CNK)*CD + h*CDH;

    wmma::fragment<wmma::accumulator,16,16,8,float> acc[2][2];
    #pragma unroll
    for(int i=0;i<2;i++)
        #pragma unroll
        for(int j=0;j<2;j++) wmma::fill_fragment(acc[i][j], 0.0f);

    for(int kk0=0; kk0<CNK; kk0+=32){
        // P tile 128x32
        #pragma unroll
        for(int i=0;i<4;i++){
            int id = tid + i*256;
            int r = id >> 3, c4 = id & 7;
            float4 v = *(const float4*)&Pb[(size_t)(q0+r)*CNK + kk0 + c4*4];
            float* d = &Ps[r][c4*4];
            d[0]=to_tf32(v.x); d[1]=to_tf32(v.y); d[2]=to_tf32(v.z); d[3]=to_tf32(v.w);
        }
        // V tile 32x64
        #pragma unroll
        for(int i=0;i<2;i++){
            int id = tid + i*256;
            int r = id >> 4, c4 = id & 15;
            float4 v = *(const float4*)&Vb[(size_t)(kk0+r)*CD + c4*4];
            float* d = &Vs[r][c4*4];
            d[0]=to_tf32(v.x); d[1]=to_tf32(v.y); d[2]=to_tf32(v.z); d[3]=to_tf32(v.w);
        }
        __syncthreads();
        #pragma unroll
        for(int ks=0;ks<4;ks++){
            wmma::fragment<wmma::matrix_a,16,16,8,wmma::precision::tf32,wmma::row_major> af[2];
            wmma::fragment<wmma::matrix_b,16,16,8,wmma::precision::tf32,wmma::row_major> bf[2];
            wmma::load_matrix_sync(af[0], &Ps[wy*32][ks*8],    40);
            wmma::load_matrix_sync(af[1], &Ps[wy*32+16][ks*8], 40);
            wmma::load_matrix_sync(bf[0], &Vs[ks*8][wx*32],    72);
            wmma::load_matrix_sync(bf[1], &Vs[ks*8][wx*32+16], 72);
            #pragma unroll
            for(int i=0;i<2;i++)
                #pragma unroll
                for(int j=0;j<2;j++)
                    wmma::mma_sync(acc[i][j], af[i], bf[j], acc[i][j]);
        }
        __syncthreads();
    }
    #pragma unroll
    for(int i=0;i<2;i++)
        #pragma unroll
        for(int j=0;j<2;j++)
            wmma::store_matrix_sync(
                &ctx[(size_t)(b*CNQ + q0 + wy*32 + i*16)*CD + h*CDH + wx*32 + j*16],
                acc[i][j], CD, wmma::mem_row_major);
}

// ------------------------- h+ffn, double LN, scatter-add -------------------
__global__ void k_final(const float* __restrict__ h, const float* __restrict__ t2,
                        const float* __restrict__ os, const float* __restrict__ ob,
                        const float* __restrict__ es, const float* __restrict__ eb,
                        const int*   __restrict__ qidx,
                        float* __restrict__ upd, float* __restrict__ outp){
    __shared__ float sbuf[16];
    int row = blockIdx.x;
    int b = row >> 9, p = row & (CNQ-1);
    int t = threadIdx.x;
    float x = h[(size_t)row*CD + t] + t2[(size_t)row*CD + t];

    float s1 = x, s2 = x*x;
    #pragma unroll
    for(int o=16;o>0;o>>=1){
        s1 += __shfl_xor_sync(0xffffffffu, s1, o);
        s2 += __shfl_xor_sync(0xffffffffu, s2, o);
    }
    if((t&31)==0){ sbuf[t>>5]=s1; sbuf[8+(t>>5)]=s2; }
    __syncthreads();
    s1=0.f; s2=0.f;
    #pragma unroll
    for(int i=0;i<8;i++){ s1+=sbuf[i]; s2+=sbuf[8+i]; }
    float mean = s1*(1.0f/CD);
    float var  = s2*(1.0f/CD) - mean*mean;
    float rstd = rsqrtf(var + 1e-5f);
    float y = (x-mean)*rstd*os[t] + ob[t];
    __syncthreads();

    s1 = y; s2 = y*y;
    #pragma unroll
    for(int o=16;o>0;o>>=1){
        s1 += __shfl_xor_sync(0xffffffffu, s1, o);
        s2 += __shfl_xor_sync(0xffffffffu, s2, o);
    }
    if((t&31)==0){ sbuf[t>>5]=s1; sbuf[8+(t>>5)]=s2; }
    __syncthreads();
    s1=0.f; s2=0.f;
    #pragma unroll
    for(int i=0;i<8;i++){ s1+=sbuf[i]; s2+=sbuf[8+i]; }
    float mean2 = s1*(1.0f/CD);
    float var2  = s2*(1.0f/CD) - mean2*mean2;
    float rstd2 = rsqrtf(var2 + 1e-5f);
    float res = (y-mean2)*rstd2*es[t] + eb[t];

    int node = qidx[p];
    size_t off = ((size_t)(b*CNS + node))*CD + t;
    atomicAdd(&upd[off],  res);
    atomicAdd(&outp[off], res);
}

// ------------------------- launch ------------------------------------------
extern "C" void kernel_launch(void* const* d_in, const int* in_sizes, int n_in,
                              void* d_out, int out_size){
    const float* in_upd  = (const float*)d_in[0];
    const float* emb     = (const float*)d_in[1];
    const float* maskL   = (const float*)d_in[2];
    const float* Wq      = (const float*)d_in[3];
    const float* Wk      = (const float*)d_in[4];
    const float* Wv      = (const float*)d_in[5];
    const float* Wo      = (const float*)d_in[6];
    const float* W1      = (const float*)d_in[7];
    const float* b1      = (const float*)d_in[8];
    const float* W2      = (const float*)d_in[9];
    const float* b2      = (const float*)d_in[10];
    const float* sys_s   = (const float*)d_in[11];
    const float* sys_b   = (const float*)d_in[12];
    const float* eff_s   = (const float*)d_in[13];
    const float* eff_b   = (const float*)d_in[14];
    const float* in_s    = (const float*)d_in[15];
    const float* in_b    = (const float*)d_in[16];
    const float* out_s   = (const float*)d_in[17];
    const float* out_b   = (const float*)d_in[18];
    const int*   qidxL   = (const int*)d_in[19];
    const int*   kidxL   = (const int*)d_in[20];
    float* outp = (float*)d_out;

    float *upd,*qb,*kb,*Qb,*Kb,*Vb,*ctx,*hb,*t1,*t2,*Sb;
    cudaGetSymbolAddress((void**)&upd, g_upd);
    cudaGetSymbolAddress((void**)&qb,  g_q);
    cudaGetSymbolAddress((void**)&kb,  g_k);
    cudaGetSymbolAddress((void**)&Qb,  g_Qp);
    cudaGetSymbolAddress((void**)&Kb,  g_Kp);
    cudaGetSymbolAddress((void**)&Vb,  g_Vp);
    cudaGetSymbolAddress((void**)&ctx, g_ctx);
    cudaGetSymbolAddress((void**)&hb,  g_h);
    cudaGetSymbolAddress((void**)&t1,  g_t1);
    cudaGetSymbolAddress((void**)&t2,  g_t2);
    cudaGetSymbolAddress((void**)&Sb,  g_S);

    cudaMemsetAsync(d_out, 0, (size_t)out_size * sizeof(float));
    k_copy_upd<<<(CB*CNS*CD/4)/256, 256>>>((const float4*)in_upd);

    for(int l=0;l<CL;l++){
        const int*   qi  = qidxL + l*CNQ;
        const int*   ki  = kidxL + l*CNK;
        const float* msk = maskL + (size_t)l*CNQ*CNK;

        k_gather_ln<<<CB*CNQ, 256>>>(upd, emb, qi, sys_s, sys_b, qb, CNQ);
        k_gather_ln<<<CB*CNK, 256>>>(upd, emb, ki, sys_s, sys_b, kb, CNK);

        k_gemm_tc<<<dim3(CB*CNQ/128, 4), 256>>>(qb, Wq, nullptr, Qb, 0);
        k_gemm_tc<<<dim3(CB*CNK/128, 4), 256>>>(kb, Wk, nullptr, Kb, 0);
        k_gemm_tc<<<dim3(CB*CNK/128, 4), 256>>>(kb, Wv, nullptr, Vb, 0);

        k_qk     <<<dim3(CNQ/64, CNK/128, CB*CH), 256>>>(Qb, Kb, Sb);
        k_softmax<<<dim3(CNQ, CB*CH), 256>>>(Sb, msk);
        k_pv     <<<dim3(CNQ/128, CB*CH), 256>>>(Sb, Vb, ctx);

        k_gemm_tc<<<dim3(CB*CNQ/128, 4), 256>>>(ctx, Wo, nullptr, t1, 0);
        k_ln  <<<CB*CNQ, 256>>>(t1, in_s, in_b, hb);

        k_gemm_tc<<<dim3(CB*CNQ/128, 4), 256>>>(hb, W1, b1, t1, 1);   // gelu
        k_gemm_tc<<<dim3(CB*CNQ/128, 4), 256>>>(t1, W2, b2, t2, 0);

        k_final<<<CB*CNQ, 256>>>(hb, t2, out_s, out_b, eff_s, eff_b,
                                 qi, upd, outp);
    }
}

// round 6
// speedup vs baseline: 4.1615x; 1.0086x over previous
#include <cuda_runtime.h>
#include <mma.h>
#include <math.h>

using namespace nvcuda;

#define CB  32
#define CNS 4096
#define CD  256
#define CH  4
#define CDH 64
#define CL  6
#define CNQ 512
#define CNK 1024
#define SCALE_F 0.125f   // 1/sqrt(64)

// ------------------------- scratch (device globals; no allocs) -------------
__device__ float g_upd[CB*CNS*CD];
__device__ float g_q  [CB*CNQ*CD];
__device__ float g_k  [CB*CNK*CD];
__device__ float g_Qp [CB*CNQ*CD];
__device__ float g_Kp [CB*CNK*CD];
__device__ float g_Vp [CB*CNK*CD];
__device__ float g_ctx[CB*CNQ*CD];
__device__ float g_h  [CB*CNQ*CD];
__device__ float g_t1 [CB*CNQ*CD];
__device__ float g_t2 [CB*CNQ*CD];

// ------------------------- helpers ----------------------------------------
__device__ __forceinline__ float gelu_tanh(float x){
    float x3 = x*x*x;
    float t  = tanhf(0.7978845608028654f * (x + 0.044715f * x3));
    return 0.5f * x * (1.0f + t);
}
__device__ __forceinline__ float to_tf32(float x){
    return wmma::__float_to_tf32(x);
}

// ------------------------- init copy ---------------------------------------
__global__ void k_copy_upd(const float4* __restrict__ src){
    size_t i = (size_t)blockIdx.x * blockDim.x + threadIdx.x;
    ((float4*)g_upd)[i] = src[i];
}

// ------------------------- gather + LayerNorm ------------------------------
__global__ void k_gather_ln(const float* __restrict__ upd,
                            const float* __restrict__ emb,
                            const int*   __restrict__ idx,
                            const float* __restrict__ sc,
                            const float* __restrict__ bi,
                            float* __restrict__ out, int N){
    __shared__ float sbuf[16];
    int row = blockIdx.x;
    int b = row / N, p = row - b*N;
    int node = idx[p];
    int t = threadIdx.x;
    float x = emb[(size_t)node*CD + t] + upd[((size_t)b*CNS + node)*CD + t];
    float s1 = x, s2 = x*x;
    #pragma unroll
    for(int o=16;o>0;o>>=1){
        s1 += __shfl_xor_sync(0xffffffffu, s1, o);
        s2 += __shfl_xor_sync(0xffffffffu, s2, o);
    }
    if((t&31)==0){ sbuf[t>>5]=s1; sbuf[8+(t>>5)]=s2; }
    __syncthreads();
    s1=0.f; s2=0.f;
    #pragma unroll
    for(int i=0;i<8;i++){ s1+=sbuf[i]; s2+=sbuf[8+i]; }
    float mean = s1 * (1.0f/CD);
    float var  = s2 * (1.0f/CD) - mean*mean;
    float rstd = rsqrtf(var + 1e-5f);
    out[(size_t)row*CD + t] = (x-mean)*rstd*sc[t] + bi[t];
}

// ------------------------- plain row LayerNorm -----------------------------
__global__ void k_ln(const float* __restrict__ in,
                     const float* __restrict__ sc,
                     const float* __restrict__ bi,
                     float* __restrict__ out){
    __shared__ float sbuf[16];
    int row = blockIdx.x;
    int t = threadIdx.x;
    float x = in[(size_t)row*CD + t];
    float s1 = x, s2 = x*x;
    #pragma unroll
    for(int o=16;o>0;o>>=1){
        s1 += __shfl_xor_sync(0xffffffffu, s1, o);
        s2 += __shfl_xor_sync(0xffffffffu, s2, o);
    }
    if((t&31)==0){ sbuf[t>>5]=s1; sbuf[8+(t>>5)]=s2; }
    __syncthreads();
    s1=0.f; s2=0.f;
    #pragma unroll
    for(int i=0;i<8;i++){ s1+=sbuf[i]; s2+=sbuf[8+i]; }
    float mean = s1 * (1.0f/CD);
    float var  = s2 * (1.0f/CD) - mean*mean;
    float rstd = rsqrtf(var + 1e-5f);
    out[(size_t)row*CD + t] = (x-mean)*rstd*sc[t] + bi[t];
}

// ===================== TF32 WMMA dense GEMM (128x128 tile) =================
// C[M,256] = A[M,256] @ W[256,256] (+bias)(+gelu). 8 warps as 4x2,
// warp tile 32x64 = 2x4 m16n16k8 frags. act: 0 none, 1 gelu.
__global__ void __launch_bounds__(256)
k_gemm_tc(const float* __restrict__ A, const float* __restrict__ W,
          const float* __restrict__ bias, float* __restrict__ C, int act){
    __shared__ __align__(16) float As[128][36];
    __shared__ __align__(16) float Bs[32][132];
    __shared__ __align__(16) float BiasS[16][132];
    int tid = threadIdx.x;
    int w = tid >> 5;
    int wy = w >> 1, wx = w & 1;           // 4 x 2 warps
    int bm0 = blockIdx.x * 128;
    int bn0 = blockIdx.y * 128;

    wmma::fragment<wmma::accumulator,16,16,8,float> acc[2][4];
    #pragma unroll
    for(int i=0;i<2;i++)
        #pragma unroll
        for(int j=0;j<4;j++) wmma::fill_fragment(acc[i][j], 0.0f);

    for(int k0=0;k0<CD;k0+=32){
        // A tile 128x32
        #pragma unroll
        for(int i=0;i<4;i++){
            int id = tid + i*256;
            int r = id >> 3, c4 = id & 7;
            float4 v = *(const float4*)&A[(size_t)(bm0+r)*CD + k0 + c4*4];
            float* d = &As[r][c4*4];
            d[0]=to_tf32(v.x); d[1]=to_tf32(v.y); d[2]=to_tf32(v.z); d[3]=to_tf32(v.w);
        }
        // B tile 32x128
        #pragma unroll
        for(int i=0;i<4;i++){
            int id = tid + i*256;
            int r = id >> 5, c4 = id & 31;
            float4 v = *(const float4*)&W[(size_t)(k0+r)*CD + bn0 + c4*4];
            float* d = &Bs[r][c4*4];
            d[0]=to_tf32(v.x); d[1]=to_tf32(v.y); d[2]=to_tf32(v.z); d[3]=to_tf32(v.w);
        }
        __syncthreads();
        #pragma unroll
        for(int ks=0;ks<4;ks++){
            wmma::fragment<wmma::matrix_a,16,16,8,wmma::precision::tf32,wmma::row_major> af[2];
            wmma::fragment<wmma::matrix_b,16,16,8,wmma::precision::tf32,wmma::row_major> bf[4];
            wmma::load_matrix_sync(af[0], &As[wy*32][ks*8],    36);
            wmma::load_matrix_sync(af[1], &As[wy*32+16][ks*8], 36);
            #pragma unroll
            for(int j=0;j<4;j++)
                wmma::load_matrix_sync(bf[j], &Bs[ks*8][wx*64 + j*16], 132);
            #pragma unroll
            for(int i=0;i<2;i++)
                #pragma unroll
                for(int j=0;j<4;j++)
                    wmma::mma_sync(acc[i][j], af[i], bf[j], acc[i][j]);
        }
        __syncthreads();
    }

    if(bias){
        #pragma unroll
        for(int i=0;i<8;i++){
            int id = tid + i*256;      // 16x128
            int r = id >> 7, c = id & 127;
            BiasS[r][c] = bias[bn0 + c];
        }
        __syncthreads();
        #pragma unroll
        for(int j=0;j<4;j++){
            wmma::fragment<wmma::accumulator,16,16,8,float> bfr;
            wmma::load_matrix_sync(bfr, &BiasS[0][wx*64 + j*16], 132, wmma::mem_row_major);
            #pragma unroll
            for(int i=0;i<2;i++)
                #pragma unroll
                for(int e=0;e<bfr.num_elements;e++)
                    acc[i][j].x[e] += bfr.x[e];
        }
    }
    if(act==1){
        #pragma unroll
        for(int i=0;i<2;i++)
            #pragma unroll
            for(int j=0;j<4;j++)
                #pragma unroll
                for(int e=0;e<acc[i][j].num_elements;e++)
                    acc[i][j].x[e] = gelu_tanh(acc[i][j].x[e]);
    }
    #pragma unroll
    for(int i=0;i<2;i++)
        #pragma unroll
        for(int j=0;j<4;j++)
            wmma::store_matrix_sync(
                &C[(size_t)(bm0 + wy*32 + i*16)*CD + bn0 + wx*64 + j*16],
                acc[i][j], CD, wmma::mem_row_major);
}

// ===================== fused flash attention (TF32 WMMA) ===================
// grid (NQ/64, B*H), 256 thr = 8 warps. Q tile 64 rows, k tiles of 128.
// S and online softmax live entirely in smem/regs; O in wmma acc fragments.
// Row-dependent alpha / 1/denom rescale done via replicated-matrix acc frags
// (layout-agnostic).
#define FLASH_SMEM_FLOATS (64*68 + 128*68 + 64*132 + 64*20)
__global__ void __launch_bounds__(256)
k_flash(const float* __restrict__ Q, const float* __restrict__ K,
        const float* __restrict__ V, const float* __restrict__ mask,
        float* __restrict__ ctx){
    extern __shared__ __align__(16) float sm[];
    float* Qs  = sm;                    // [64][68]  q (pre-scaled, tf32)
    float* KVs = Qs  + 64*68;           // [128][68] K then V (tf32)
    float* Ss  = KVs + 128*68;          // [64][132] scores -> probs (tf32)
    float* aM  = Ss  + 64*132;          // [64][20]  per-row alpha / inv-denom

    int tid = threadIdx.x;
    int w = tid >> 5, lane = tid & 31;
    int wy = w >> 2, wx = w & 3;        // S phase: 2x4 warps (32q x 32k)
    int wq = w >> 1, wd = w & 1;        // PV phase: 4x2 warps (16q x 32d)
    int q0 = blockIdx.x * 64;
    int bh = blockIdx.y;
    int b = bh >> 2, h = bh & 3;

    const float* Qb = Q + ((size_t)(b*CNQ + q0))*CD + h*CDH;
    const float* Kb = K + ((size_t)b*CNK)*CD + h*CDH;
    const float* Vb = V + ((size_t)b*CNK)*CD + h*CDH;

    // load Q (64x64), pre-scaled by SCALE_F
    #pragma unroll
    for(int i=0;i<4;i++){
        int id = tid + i*256;
        int r = id >> 4, c4 = id & 15;
        float4 v = *(const float4*)&Qb[(size_t)r*CD + c4*4];
        float* d = &Qs[r*68 + c4*4];
        d[0]=to_tf32(v.x*SCALE_F); d[1]=to_tf32(v.y*SCALE_F);
        d[2]=to_tf32(v.z*SCALE_F); d[3]=to_tf32(v.w*SCALE_F);
    }

    float m_run[8], d_run[8];
    #pragma unroll
    for(int r=0;r<8;r++){ m_run[r] = -INFINITY; d_run[r] = 0.f; }

    wmma::fragment<wmma::accumulator,16,16,8,float> o[2];
    wmma::fill_fragment(o[0], 0.0f);
    wmma::fill_fragment(o[1], 0.0f);

    for(int k0=0; k0<CNK; k0+=128){
        // ---- load K tile 128x64 ----
        #pragma unroll
        for(int i=0;i<8;i++){
            int id = tid + i*256;
            int r = id >> 4, c4 = id & 15;
            float4 v = *(const float4*)&Kb[(size_t)(k0+r)*CD + c4*4];
            float* d = &KVs[r*68 + c4*4];
            d[0]=to_tf32(v.x); d[1]=to_tf32(v.y); d[2]=to_tf32(v.z); d[3]=to_tf32(v.w);
        }
        __syncthreads();

        // ---- S = Qs @ K^T  (64x128) ----
        {
            wmma::fragment<wmma::accumulator,16,16,8,float> s[2][2];
            #pragma unroll
            for(int i=0;i<2;i++)
                #pragma unroll
                for(int j=0;j<2;j++) wmma::fill_fragment(s[i][j], 0.0f);
            #pragma unroll
            for(int d8=0; d8<CDH; d8+=8){
                wmma::fragment<wmma::matrix_a,16,16,8,wmma::precision::tf32,wmma::row_major> af[2];
                wmma::fragment<wmma::matrix_b,16,16,8,wmma::precision::tf32,wmma::col_major> bf[2];
                wmma::load_matrix_sync(af[0], &Qs[(wy*32)*68 + d8],      68);
                wmma::load_matrix_sync(af[1], &Qs[(wy*32+16)*68 + d8],   68);
                wmma::load_matrix_sync(bf[0], &KVs[(wx*32)*68 + d8],     68);
                wmma::load_matrix_sync(bf[1], &KVs[(wx*32+16)*68 + d8],  68);
                #pragma unroll
                for(int i=0;i<2;i++)
                    #pragma unroll
                    for(int j=0;j<2;j++)
                        wmma::mma_sync(s[i][j], af[i], bf[j], s[i][j]);
            }
            #pragma unroll
            for(int i=0;i<2;i++)
                #pragma unroll
                for(int j=0;j<2;j++)
                    wmma::store_matrix_sync(&Ss[(wy*32+i*16)*132 + wx*32 + j*16],
                                            s[i][j], 132, wmma::mem_row_major);
        }
        __syncthreads();

        // ---- load V tile into KVs (K reads are done) ----
        #pragma unroll
        for(int i=0;i<8;i++){
            int id = tid + i*256;
            int r = id >> 4, c4 = id & 15;
            float4 v = *(const float4*)&Vb[(size_t)(k0+r)*CD + c4*4];
            float* d = &KVs[r*68 + c4*4];
            d[0]=to_tf32(v.x); d[1]=to_tf32(v.y); d[2]=to_tf32(v.z); d[3]=to_tf32(v.w);
        }

        // ---- masked online softmax: warp w owns q rows [w*8, w*8+8) ----
        #pragma unroll
        for(int r=0;r<8;r++){
            int row = w*8 + r;
            float4 s4 = *(float4*)&Ss[row*132 + lane*4];
            float4 m4 = *(const float4*)&mask[(size_t)(q0+row)*CNK + k0 + lane*4];
            float v0 = (m4.x>0.5f)? s4.x : -1e9f;
            float v1 = (m4.y>0.5f)? s4.y : -1e9f;
            float v2 = (m4.z>0.5f)? s4.z : -1e9f;
            float v3 = (m4.w>0.5f)? s4.w : -1e9f;
            float mx = fmaxf(fmaxf(v0,v1), fmaxf(v2,v3));
            #pragma unroll
            for(int off=16;off>0;off>>=1)
                mx = fmaxf(mx, __shfl_xor_sync(0xffffffffu, mx, off));
            float mn = fmaxf(m_run[r], mx);
            float alpha = __expf(m_run[r] - mn);
            float p0 = __expf(v0-mn), p1 = __expf(v1-mn);
            float p2 = __expf(v2-mn), p3 = __expf(v3-mn);
            float ps = (p0+p1)+(p2+p3);
            #pragma unroll
            for(int off=16;off>0;off>>=1)
                ps += __shfl_xor_sync(0xffffffffu, ps, off);
            d_run[r] = d_run[r]*alpha + ps;
            m_run[r] = mn;
            float4 pw = make_float4(to_tf32(p0), to_tf32(p1), to_tf32(p2), to_tf32(p3));
            *(float4*)&Ss[row*132 + lane*4] = pw;
            if(lane < 16) aM[row*20 + lane] = alpha;
        }
        __syncthreads();

        // ---- O = O*alpha + P @ V ----
        {
            wmma::fragment<wmma::accumulator,16,16,8,float> afr;
            wmma::load_matrix_sync(afr, &aM[(wq*16)*20], 20, wmma::mem_row_major);
            #pragma unroll
            for(int e=0;e<afr.num_elements;e++){
                o[0].x[e] *= afr.x[e];
                o[1].x[e] *= afr.x[e];
            }
            #pragma unroll
            for(int ks=0;ks<16;ks++){
                wmma::fragment<wmma::matrix_a,16,16,8,wmma::precision::tf32,wmma::row_major> pa;
                wmma::fragment<wmma::matrix_b,16,16,8,wmma::precision::tf32,wmma::row_major> vb[2];
                wmma::load_matrix_sync(pa, &Ss[(wq*16)*132 + ks*8], 132);
                wmma::load_matrix_sync(vb[0], &KVs[(ks*8)*68 + wd*32],      68);
                wmma::load_matrix_sync(vb[1], &KVs[(ks*8)*68 + wd*32 + 16], 68);
                wmma::mma_sync(o[0], pa, vb[0], o[0]);
                wmma::mma_sync(o[1], pa, vb[1], o[1]);
            }
        }
        __syncthreads();
    }

    // ---- finalize: divide by denom, store ----
    #pragma unroll
    for(int r=0;r<8;r++){
        int row = w*8 + r;
        if(lane < 16) aM[row*20 + lane] = 1.0f / d_run[r];
    }
    __syncthreads();
    {
        wmma::fragment<wmma::accumulator,16,16,8,float> ifr;
        wmma::load_matrix_sync(ifr, &aM[(wq*16)*20], 20, wmma::mem_row_major);
        #pragma unroll
        for(int e=0;e<ifr.num_elements;e++){
            o[0].x[e] *= ifr.x[e];
            o[1].x[e] *= ifr.x[e];
        }
        float* cb = ctx + ((size_t)(b*CNQ + q0 + wq*16))*CD + h*CDH + wd*32;
        wmma::store_matrix_sync(cb,      o[0], CD, wmma::mem_row_major);
        wmma::store_matrix_sync(cb + 16, o[1], CD, wmma::mem_row_major);
    }
}

// ------------------------- h+ffn, double LN, scatter-add -------------------
__global__ void k_final(const float* __restrict__ h, const float* __restrict__ t2,
                        const float* __restrict__ os, const float* __restrict__ ob,
                        const float* __restrict__ es, const float* __restrict__ eb,
                        const int*   __restrict__ qidx,
                        float* __restrict__ upd, float* __restrict__ outp){
    __shared__ float sbuf[16];
    int row = blockIdx.x;
    int b = row >> 9, p = row & (CNQ-1);
    int t = threadIdx.x;
    float x = h[(size_t)row*CD + t] + t2[(size_t)row*CD + t];

    float s1 = x, s2 = x*x;
    #pragma unroll
    for(int o=16;o>0;o>>=1){
        s1 += __shfl_xor_sync(0xffffffffu, s1, o);
        s2 += __shfl_xor_sync(0xffffffffu, s2, o);
    }
    if((t&31)==0){ sbuf[t>>5]=s1; sbuf[8+(t>>5)]=s2; }
    __syncthreads();
    s1=0.f; s2=0.f;
    #pragma unroll
    for(int i=0;i<8;i++){ s1+=sbuf[i]; s2+=sbuf[8+i]; }
    float mean = s1*(1.0f/CD);
    float var  = s2*(1.0f/CD) - mean*mean;
    float rstd = rsqrtf(var + 1e-5f);
    float y = (x-mean)*rstd*os[t] + ob[t];
    __syncthreads();

    s1 = y; s2 = y*y;
    #pragma unroll
    for(int o=16;o>0;o>>=1){
        s1 += __shfl_xor_sync(0xffffffffu, s1, o);
        s2 += __shfl_xor_sync(0xffffffffu, s2, o);
    }
    if((t&31)==0){ sbuf[t>>5]=s1; sbuf[8+(t>>5)]=s2; }
    __syncthreads();
    s1=0.f; s2=0.f;
    #pragma unroll
    for(int i=0;i<8;i++){ s1+=sbuf[i]; s2+=sbuf[8+i]; }
    float mean2 = s1*(1.0f/CD);
    float var2  = s2*(1.0f/CD) - mean2*mean2;
    float rstd2 = rsqrtf(var2 + 1e-5f);
    float res = (y-mean2)*rstd2*es[t] + eb[t];

    int node = qidx[p];
    size_t off = ((size_t)(b*CNS + node))*CD + t;
    atomicAdd(&upd[off],  res);
    atomicAdd(&outp[off], res);
}

// ------------------------- launch ------------------------------------------
extern "C" void kernel_launch(void* const* d_in, const int* in_sizes, int n_in,
                              void* d_out, int out_size){
    const float* in_upd  = (const float*)d_in[0];
    const float* emb     = (const float*)d_in[1];
    const float* maskL   = (const float*)d_in[2];
    const float* Wq      = (const float*)d_in[3];
    const float* Wk      = (const float*)d_in[4];
    const float* Wv      = (const float*)d_in[5];
    const float* Wo      = (const float*)d_in[6];
    const float* W1      = (const float*)d_in[7];
    const float* b1      = (const float*)d_in[8];
    const float* W2      = (const float*)d_in[9];
    const float* b2      = (const float*)d_in[10];
    const float* sys_s   = (const float*)d_in[11];
    const float* sys_b   = (const float*)d_in[12];
    const float* eff_s   = (const float*)d_in[13];
    const float* eff_b   = (const float*)d_in[14];
    const float* in_s    = (const float*)d_in[15];
    const float* in_b    = (const float*)d_in[16];
    const float* out_s   = (const float*)d_in[17];
    const float* out_b   = (const float*)d_in[18];
    const int*   qidxL   = (const int*)d_in[19];
    const int*   kidxL   = (const int*)d_in[20];
    float* outp = (float*)d_out;

    float *upd,*qb,*kb,*Qb,*Kb,*Vb,*ctx,*hb,*t1,*t2;
    cudaGetSymbolAddress((void**)&upd, g_upd);
    cudaGetSymbolAddress((void**)&qb,  g_q);
    cudaGetSymbolAddress((void**)&kb,  g_k);
    cudaGetSymbolAddress((void**)&Qb,  g_Qp);
    cudaGetSymbolAddress((void**)&Kb,  g_Kp);
    cudaGetSymbolAddress((void**)&Vb,  g_Vp);
    cudaGetSymbolAddress((void**)&ctx, g_ctx);
    cudaGetSymbolAddress((void**)&hb,  g_h);
    cudaGetSymbolAddress((void**)&t1,  g_t1);
    cudaGetSymbolAddress((void**)&t2,  g_t2);

    const int flash_smem = FLASH_SMEM_FLOATS * (int)sizeof(float);  // ~91 KB
    cudaFuncSetAttribute(k_flash, cudaFuncAttributeMaxDynamicSharedMemorySize,
                         flash_smem);

    cudaMemsetAsync(d_out, 0, (size_t)out_size * sizeof(float));
    k_copy_upd<<<(CB*CNS*CD/4)/256, 256>>>((const float4*)in_upd);

    for(int l=0;l<CL;l++){
        const int*   qi  = qidxL + l*CNQ;
        const int*   ki  = kidxL + l*CNK;
        const float* msk = maskL + (size_t)l*CNQ*CNK;

        k_gather_ln<<<CB*CNQ, 256>>>(upd, emb, qi, sys_s, sys_b, qb, CNQ);
        k_gather_ln<<<CB*CNK, 256>>>(upd, emb, ki, sys_s, sys_b, kb, CNK);

        k_gemm_tc<<<dim3(CB*CNQ/128, 2), 256>>>(qb, Wq, nullptr, Qb, 0);
        k_gemm_tc<<<dim3(CB*CNK/128, 2), 256>>>(kb, Wk, nullptr, Kb, 0);
        k_gemm_tc<<<dim3(CB*CNK/128, 2), 256>>>(kb, Wv, nullptr, Vb, 0);

        k_flash<<<dim3(CNQ/64, CB*CH), 256, flash_smem>>>(Qb, Kb, Vb, msk, ctx);

        k_gemm_tc<<<dim3(CB*CNQ/128, 2), 256>>>(ctx, Wo, nullptr, t1, 0);
        k_ln  <<<CB*CNQ, 256>>>(t1, in_s, in_b, hb);

        k_gemm_tc<<<dim3(CB*CNQ/128, 2), 256>>>(hb, W1, b1, t1, 1);   // gelu
        k_gemm_tc<<<dim3(CB*CNQ/128, 2), 256>>>(t1, W2, b2, t2, 0);

        k_final<<<CB*CNQ, 256>>>(hb, t2, out_s, out_b, eff_s, eff_b,
                                 qi, upd, outp);
    }
}